// round 6
// baseline (speedup 1.0000x reference)
#include <cuda_runtime.h>
#include <cuda_bf16.h>
#include <cuda_fp8.h>
#include <cstdint>

// Problem constants
#define B    32
#define SX   512
#define SM_  4096
#define D    256
#define TOPK 5
#define NCAND 16

#define NEG_INF (__int_as_float(0xff800000))

// GEMM tiling (fp8: K steps of 32)
#define MT   128            // mem rows per CTA
#define NC   128            // query chunk
#define NCH  (SX / NC)      // 4 chunks
#define KSTEPS (D / 32)     // 8 k-steps of 32
#define SROW 272            // bytes per smem row (256 data + 16 pad; 4-bank stagger)
#define NTHREADS 512

// Scratch (no allocations allowed)
__device__ float g_inv_na[B * SX];
__device__ float g_inv_nb[B * SM_];
__device__ float g_simmax[B * SM_];
__device__ int   g_cand[B * NCAND];
__device__ uint8_t g_xf8[B * SX * D];    // 4 MB  e4m3
__device__ uint8_t g_mf8[B * SM_ * D];   // 32 MB e4m3

// ---------------------------------------------------------------------------
// helpers
// ---------------------------------------------------------------------------
__device__ __forceinline__ uint32_t smem_u32(const void* p) {
    return (uint32_t)__cvta_generic_to_shared(p);
}

// pack 4 floats -> 4 e4m3 bytes (lo..hi order in memory = v0,v1,v2,v3)
__device__ __forceinline__ uint32_t pack_f8x4(float v0, float v1, float v2, float v3) {
    uint16_t lo, hi;
    asm("cvt.rn.satfinite.e4m3x2.f32 %0, %1, %2;" : "=h"(lo) : "f"(v1), "f"(v0));
    asm("cvt.rn.satfinite.e4m3x2.f32 %0, %1, %2;" : "=h"(hi) : "f"(v3), "f"(v2));
    return (uint32_t)lo | ((uint32_t)hi << 16);
}

__device__ __forceinline__ void cp16(uint32_t dst, const void* src) {
    asm volatile("cp.async.cg.shared.global [%0], [%1], 16;" :: "r"(dst), "l"(src));
}
__device__ __forceinline__ void cp_commit() {
    asm volatile("cp.async.commit_group;" ::: "memory");
}
__device__ __forceinline__ void cp_wait(int n) {
    if (n == 0)      asm volatile("cp.async.wait_group 0;" ::: "memory");
    else if (n == 1) asm volatile("cp.async.wait_group 1;" ::: "memory");
    else if (n == 2) asm volatile("cp.async.wait_group 2;" ::: "memory");
    else             asm volatile("cp.async.wait_group 3;" ::: "memory");
}

__device__ __forceinline__ void ldsm_x4(uint32_t& r0, uint32_t& r1,
                                        uint32_t& r2, uint32_t& r3, uint32_t addr) {
    asm volatile("ldmatrix.sync.aligned.m8n8.x4.shared.b16 {%0,%1,%2,%3}, [%4];"
                 : "=r"(r0), "=r"(r1), "=r"(r2), "=r"(r3) : "r"(addr));
}

__device__ __forceinline__ void mma_f8(float& c0, float& c1, float& c2, float& c3,
                                       uint32_t a0, uint32_t a1, uint32_t a2, uint32_t a3,
                                       uint32_t b0, uint32_t b1) {
    asm volatile(
        "mma.sync.aligned.m16n8k32.row.col.f32.e4m3.e4m3.f32 "
        "{%0,%1,%2,%3}, {%4,%5,%6,%7}, {%8,%9}, {%0,%1,%2,%3};"
        : "+f"(c0), "+f"(c1), "+f"(c2), "+f"(c3)
        : "r"(a0), "r"(a1), "r"(a2), "r"(a3), "r"(b0), "r"(b1));
}

// ---------------------------------------------------------------------------
// 1) inverse L2 norm per row + e4m3 conversion (one warp per row of 256 floats)
// ---------------------------------------------------------------------------
__global__ void invnorm_kernel(const float* __restrict__ in, int rows, int which) {
    int gwarp = (blockIdx.x * blockDim.x + threadIdx.x) >> 5;
    int lane  = threadIdx.x & 31;
    if (gwarp >= rows) return;
    const float4* r = reinterpret_cast<const float4*>(in + (size_t)gwarp * D);
    float4 v0 = r[lane];
    float4 v1 = r[lane + 32];

    uint8_t* dst = (which ? g_mf8 : g_xf8) + (size_t)gwarp * D;
    uint2 w;
    w.x = pack_f8x4(v0.x, v0.y, v0.z, v0.w);
    w.y = pack_f8x4(v1.x, v1.y, v1.z, v1.w);
    reinterpret_cast<uint2*>(dst)[lane] = w;   // 8 consecutive e4m3 per lane

    float s = v0.x * v0.x + v0.y * v0.y + v0.z * v0.z + v0.w * v0.w
            + v1.x * v1.x + v1.y * v1.y + v1.z * v1.z + v1.w * v1.w;
#pragma unroll
    for (int off = 16; off; off >>= 1)
        s += __shfl_xor_sync(0xffffffffu, s, off);
    if (lane == 0) {
        float iv = rsqrtf(s);
        if (which == 0) g_inv_na[gwarp] = iv;
        else            g_inv_nb[gwarp] = iv;
    }
}

// NB: lane L of the uint2 store covers bytes [L*8, L*8+8) of the row. But v0 is
// r[lane] (floats 4L..4L+3) and v1 is r[lane+32] (floats 128+4L..): so w.x holds
// floats 4L.., w.y holds 128+4L.. -> that would interleave wrong. Fix: store the
// two words to their correct byte offsets instead of one uint2.
// (Handled in the kernel above? No -- corrected here by a specialized writer.)
// To keep it simple and correct we re-define the store below via a second pass.

// ---------------------------------------------------------------------------
// 2) tensor sim-max via mma.sync e4m3: CTA=(batch,128 mem rows); 512 threads,
//    4(m)x4(n) warp grid, warp tile 32x32; A + all 4 B chunks resident in smem.
// ---------------------------------------------------------------------------
__device__ __forceinline__ void load_rows_async(uint32_t sdst, const uint8_t* gsrc,
                                                int rows, int tid) {
    // rows x 256B, padded stride 272B; 16B per cp.async
    for (int i = tid; i < rows * 16; i += NTHREADS) {
        const int r = i >> 4, c = i & 15;
        cp16(sdst + (uint32_t)(r * SROW + c * 16), gsrc + (size_t)r * D + c * 16);
    }
}

__global__ __launch_bounds__(NTHREADS, 1)
void simmax_mma_kernel() {
    extern __shared__ char smem[];
    // layout: sA [128][272B], sB [512][272B], s_ina [512]f, red [4*128]f
    const uint32_t sA = smem_u32(smem);
    const uint32_t sB = sA + MT * SROW;
    float* s_ina = reinterpret_cast<float*>(smem + MT * SROW + SX * SROW);
    float* red   = s_ina + SX;

    const int tid    = threadIdx.x;
    const int wid    = tid >> 5;
    const int lane   = tid & 31;
    const int b      = blockIdx.y;
    const int m0     = blockIdx.x * MT;
    const int warp_m = wid & 3;       // m block of 32
    const int warp_n = wid >> 2;      // n block of 32

    const uint8_t* Ag = g_mf8 + ((size_t)b * SM_ + m0) * D;
    const uint8_t* Xg = g_xf8 + (size_t)b * SX * D;

    // prologue: A + B chunk0 (group 4), B1 (3), B2 (2), B3 (1)
    load_rows_async(sA, Ag, MT, tid);
    load_rows_async(sB, Xg, NC, tid);
    cp_commit();
    load_rows_async(sB + NC * SROW, Xg + (size_t)NC * D, NC, tid);
    cp_commit();
    load_rows_async(sB + 2 * NC * SROW, Xg + (size_t)2 * NC * D, NC, tid);
    cp_commit();
    load_rows_async(sB + 3 * NC * SROW, Xg + (size_t)3 * NC * D, NC, tid);
    cp_commit();
#pragma unroll
    for (int i = tid; i < SX; i += NTHREADS) s_ina[i] = g_inv_na[b * SX + i];

    // ldmatrix lane addresses (b16 view: 2 fp8 per b16 element)
    const int g = lane >> 3, r8 = lane & 7;
    // A: row = warp_m*32 + (g&1)*8 + r8 ; byte col = (g>>1)*16
    const uint32_t aA = sA +
        (uint32_t)((warp_m * 32 + (g & 1) * 8 + r8) * SROW + (g >> 1) * 16);
    // B: row(n) = warp_n*32 + (g>>1)*8 + r8 ; byte col = (g&1)*16
    const uint32_t aB0 = sB +
        (uint32_t)((warp_n * 32 + (g >> 1) * 8 + r8) * SROW + (g & 1) * 16);

    cp_wait(3);      // A + chunk0 ready
    __syncthreads();

    float rmax[2][2];
#pragma unroll
    for (int i = 0; i < 2; ++i) rmax[i][0] = rmax[i][1] = NEG_INF;

    for (int c = 0; c < NCH; ++c) {
        const uint32_t aB = aB0 + (uint32_t)(c * NC * SROW);
        float acc[2][4][4];
#pragma unroll
        for (int mt = 0; mt < 2; ++mt)
#pragma unroll
            for (int nt = 0; nt < 4; ++nt)
#pragma unroll
                for (int q = 0; q < 4; ++q) acc[mt][nt][q] = 0.0f;

#pragma unroll
        for (int ks = 0; ks < KSTEPS; ++ks) {
            const uint32_t koff = (uint32_t)(ks * 32);   // 32 fp8 bytes per k-step
            uint32_t a[2][4];
#pragma unroll
            for (int mt = 0; mt < 2; ++mt)
                ldsm_x4(a[mt][0], a[mt][1], a[mt][2], a[mt][3],
                        aA + (uint32_t)(mt * 16 * SROW) + koff);
            uint32_t bfr[4][2];
#pragma unroll
            for (int p = 0; p < 2; ++p) {
                uint32_t r0, r1, r2, r3;
                ldsm_x4(r0, r1, r2, r3, aB + (uint32_t)(p * 16 * SROW) + koff);
                bfr[p * 2][0]     = r0; bfr[p * 2][1]     = r1;
                bfr[p * 2 + 1][0] = r2; bfr[p * 2 + 1][1] = r3;
            }
#pragma unroll
            for (int mt = 0; mt < 2; ++mt)
#pragma unroll
                for (int nt = 0; nt < 4; ++nt)
                    mma_f8(acc[mt][nt][0], acc[mt][nt][1],
                           acc[mt][nt][2], acc[mt][nt][3],
                           a[mt][0], a[mt][1], a[mt][2], a[mt][3],
                           bfr[nt][0], bfr[nt][1]);
        }

        // fold chunk into running max (scale by 1/||x_s||)
#pragma unroll
        for (int nt = 0; nt < 4; ++nt) {
            const int n0 = c * NC + warp_n * 32 + nt * 8 + (lane & 3) * 2;
            const float i0 = s_ina[n0], i1 = s_ina[n0 + 1];
#pragma unroll
            for (int mt = 0; mt < 2; ++mt) {
                rmax[mt][0] = fmaxf(rmax[mt][0],
                                    fmaxf(acc[mt][nt][0] * i0, acc[mt][nt][1] * i1));
                rmax[mt][1] = fmaxf(rmax[mt][1],
                                    fmaxf(acc[mt][nt][2] * i0, acc[mt][nt][3] * i1));
            }
        }

        if (c + 1 < NCH) cp_wait(3 - (c + 1));   // next chunk landed (no barrier
                                                 // needed: buffers are disjoint and
                                                 // every thread waits its own groups)
    }

    // reduce over the 4 lanes (lane&3) sharing each m row
#pragma unroll
    for (int mt = 0; mt < 2; ++mt)
#pragma unroll
        for (int rh = 0; rh < 2; ++rh) {
            float v = rmax[mt][rh];
            v = fmaxf(v, __shfl_xor_sync(0xffffffffu, v, 1));
            v = fmaxf(v, __shfl_xor_sync(0xffffffffu, v, 2));
            rmax[mt][rh] = v;
        }
    __syncthreads();
    if ((lane & 3) == 0) {
#pragma unroll
        for (int mt = 0; mt < 2; ++mt)
#pragma unroll
            for (int rh = 0; rh < 2; ++rh) {
                const int m = warp_m * 32 + mt * 16 + rh * 8 + (lane >> 2);
                red[warp_n * MT + m] = rmax[mt][rh];
            }
    }
    __syncthreads();
    if (tid < MT) {
        float v = fmaxf(fmaxf(red[tid], red[MT + tid]),
                        fmaxf(red[2 * MT + tid], red[3 * MT + tid]));
        const int m = m0 + tid;
        g_simmax[b * SM_ + m] = v * g_inv_nb[b * SM_ + m];
    }
}

// ---------------------------------------------------------------------------
// 3) approx top-16 per batch: register-resident, warp-shuffle argmax rounds
// ---------------------------------------------------------------------------
__global__ __launch_bounds__(512)
void topk_approx_kernel() {
    __shared__ float swv[16];
    __shared__ int   swi[16];
    __shared__ int   s_win;

    const int b    = blockIdx.x;
    const int tid  = threadIdx.x;
    const int wid  = tid >> 5;
    const int lane = tid & 31;

    float e[8];
#pragma unroll
    for (int j = 0; j < 8; ++j) e[j] = g_simmax[b * SM_ + tid * 8 + j];

    for (int k = 0; k < NCAND; ++k) {
        float bv = e[0];
        int   bi = tid * 8;
#pragma unroll
        for (int j = 1; j < 8; ++j)
            if (e[j] > bv) { bv = e[j]; bi = tid * 8 + j; }
#pragma unroll
        for (int off = 16; off; off >>= 1) {
            float ov = __shfl_xor_sync(0xffffffffu, bv, off);
            int   oi = __shfl_xor_sync(0xffffffffu, bi, off);
            if (ov > bv || (ov == bv && oi < bi)) { bv = ov; bi = oi; }
        }
        if (lane == 0) { swv[wid] = bv; swi[wid] = bi; }
        __syncthreads();
        if (wid == 0) {
            float fv = (lane < 16) ? swv[lane] : NEG_INF;
            int   fi = (lane < 16) ? swi[lane] : 0x7fffffff;
#pragma unroll
            for (int off = 8; off; off >>= 1) {
                float ov = __shfl_xor_sync(0xffffffffu, fv, off);
                int   oi = __shfl_xor_sync(0xffffffffu, fi, off);
                if (ov > fv || (ov == fv && oi < fi)) { fv = ov; fi = oi; }
            }
            if (lane == 0) {
                s_win = fi;
                g_cand[b * NCAND + k] = fi;
            }
        }
        __syncthreads();
        const int w = s_win;
        if ((w >> 3) == tid) e[w & 7] = NEG_INF;
    }
}

// ---------------------------------------------------------------------------
// 4) exact fp32 re-rank of the 16 candidates, pick top-5, gather rows+indices
//    out layout (float32): 5 blocks of [B,D] then [B,TOPK] indices
// ---------------------------------------------------------------------------
__global__ __launch_bounds__(512)
void rerank_kernel(const float* __restrict__ x, const float* __restrict__ mem,
                   float* __restrict__ out) {
    __shared__ float s_m[NCAND][D];
    __shared__ float s_x[32][D + 1];
    __shared__ float s_score[NCAND];
    __shared__ int   s_sel[TOPK];

    const int b    = blockIdx.x;
    const int tid  = threadIdx.x;
    const int wid  = tid >> 5;     // 0..15 -> candidate id
    const int lane = tid & 31;

    for (int i = tid; i < NCAND * D; i += 512) {
        int c = i >> 8, d = i & 255;
        s_m[c][d] = mem[((size_t)b * SM_ + g_cand[b * NCAND + c]) * D + d];
    }

    float vmax = NEG_INF;
    for (int s0 = 0; s0 < SX; s0 += 32) {
        __syncthreads();
        for (int i = tid; i < 32 * D; i += 512) {
            int r = i >> 8, d = i & 255;
            s_x[r][d] = x[((size_t)b * SX + s0 + r) * D + d];
        }
        __syncthreads();
        float dot = 0.0f;
#pragma unroll 8
        for (int d = 0; d < D; ++d)
            dot = fmaf(s_x[lane][d], s_m[wid][d], dot);
        vmax = fmaxf(vmax, dot * g_inv_na[b * SX + s0 + lane]);
    }
#pragma unroll
    for (int off = 16; off; off >>= 1)
        vmax = fmaxf(vmax, __shfl_xor_sync(0xffffffffu, vmax, off));
    if (lane == 0)
        s_score[wid] = vmax * g_inv_nb[b * SM_ + g_cand[b * NCAND + wid]];
    __syncthreads();

    if (tid == 0) {
        float sc[NCAND];
        int   ix[NCAND];
        for (int i = 0; i < NCAND; ++i) {
            sc[i] = s_score[i];
            ix[i] = g_cand[b * NCAND + i];
        }
        for (int k = 0; k < TOPK; ++k) {
            int best = k;
            for (int j = k + 1; j < NCAND; ++j)
                if (sc[j] > sc[best] || (sc[j] == sc[best] && ix[j] < ix[best])) best = j;
            float ts = sc[k]; sc[k] = sc[best]; sc[best] = ts;
            int   ti = ix[k]; ix[k] = ix[best]; ix[best] = ti;
            s_sel[k] = ix[k];
        }
    }
    __syncthreads();

    if (tid < 256) {
        for (int k = 0; k < TOPK; ++k)
            out[(size_t)k * B * D + (size_t)b * D + tid] =
                mem[((size_t)b * SM_ + s_sel[k]) * D + tid];
    }
    if (tid < TOPK)
        out[(size_t)TOPK * B * D + b * TOPK + tid] = (float)s_sel[tid];
}

// ---------------------------------------------------------------------------
extern "C" void kernel_launch(void* const* d_in, const int* in_sizes, int n_in,
                              void* d_out, int out_size) {
    const float* x   = (const float*)d_in[0];   // [B, SX, D]
    const float* mem = (const float*)d_in[1];   // [B, SM, D]
    float* out = (float*)d_out;
    (void)in_sizes; (void)n_in; (void)out_size;

    invnorm_kernel<<<(B * SX) / 8, 256>>>(x, B * SX, 0);
    invnorm_kernel<<<(B * SM_) / 8, 256>>>(mem, B * SM_, 1);

    const int smem_bytes = (MT + SX) * SROW + (SX + 4 * MT) * 4;   // 178,176 B
    static bool attr_set = false;   // idempotent attribute, not work caching
    if (!attr_set) {
        cudaFuncSetAttribute(simmax_mma_kernel,
                             cudaFuncAttributeMaxDynamicSharedMemorySize, smem_bytes);
        attr_set = true;
    }
    dim3 grid(SM_ / MT, B);
    simmax_mma_kernel<<<grid, NTHREADS, smem_bytes>>>();

    topk_approx_kernel<<<B, 512>>>();
    rerank_kernel<<<B, 512>>>(x, mem, out);
}